// round 1
// baseline (speedup 1.0000x reference)
#include <cuda_runtime.h>

// Problem constants
#define IN_NODES  1152
#define OUT_NODES 10
#define IN_DIM    8
#define OUT_DIM   16
#define BATCH     256
#define COLS      (OUT_NODES * OUT_DIM)   // 160
#define KTOT      (IN_NODES * IN_DIM)     // 9216
#define ISPLIT    36                      // split-K groups for S-GEMM
#define IPB       32                      // capsules per split (36*32 = 1152)

// -------- device scratch (no allocations allowed) --------
__device__ float g_xT   [KTOT * BATCH];              // x transposed: [ik][b], 9.4 MB
__device__ float g_wc   [IN_NODES * COLS * IN_DIM];  // c-scaled W:  [i][col*8+k], 5.9 MB
__device__ float g_spart[ISPLIT * COLS * BATCH];     // S partials:  [is][col][b], 5.9 MB
__device__ float g_vT   [COLS * BATCH];              // v transposed: [col][b]
__device__ float g_c    [IN_NODES * OUT_NODES];
__device__ float g_b    [IN_NODES * OUT_NODES];

// -------- zero routing logits (per replay!) --------
__global__ void zero_b_kernel() {
    int idx = blockIdx.x * 256 + threadIdx.x;
    if (idx < IN_NODES * OUT_NODES) g_b[idx] = 0.0f;
}

// -------- transpose x [256][9216] -> xT [9216][256] --------
__global__ void transpose_x_kernel(const float* __restrict__ x) {
    __shared__ float tile[32][33];
    int ik0 = blockIdx.x * 32;   // 288 blocks
    int b0  = blockIdx.y * 32;   // 8 blocks
    int tx = threadIdx.x, ty = threadIdx.y;  // 32 x 8
#pragma unroll
    for (int r = 0; r < 32; r += 8)
        tile[ty + r][tx] = x[(size_t)(b0 + ty + r) * KTOT + ik0 + tx];
    __syncthreads();
#pragma unroll
    for (int r = 0; r < 32; r += 8)
        g_xT[(size_t)(ik0 + ty + r) * BATCH + b0 + tx] = tile[tx][ty + r];
}

// -------- c = softmax(b) over the 10 out-nodes, per in-node --------
__global__ void softmax_c_kernel() {
    int i = blockIdx.x * 128 + threadIdx.x;
    if (i >= IN_NODES) return;
    float v[OUT_NODES];
    float m = -1e30f;
#pragma unroll
    for (int j = 0; j < OUT_NODES; ++j) { v[j] = g_b[i * OUT_NODES + j]; m = fmaxf(m, v[j]); }
    float s = 0.0f;
#pragma unroll
    for (int j = 0; j < OUT_NODES; ++j) { v[j] = __expf(v[j] - m); s += v[j]; }
    float inv = 1.0f / s;
#pragma unroll
    for (int j = 0; j < OUT_NODES; ++j) g_c[i * OUT_NODES + j] = v[j] * inv;
}

// -------- wc = c[i,j] * W  (elementwise, float4) --------
__global__ void scale_w_kernel(const float* __restrict__ W) {
    int idx = blockIdx.x * 256 + threadIdx.x;          // < 368640 float4s
    const float4* W4 = (const float4*)W;
    float4* wc4 = (float4*)g_wc;
    int i = idx / 320;                 // 320 float4 per capsule row (1280 floats)
    int q = idx - i * 320;             // q = col*2 + kq
    float c = __ldg(&g_c[i * OUT_NODES + (q >> 5)]);   // q>>5 == col/16 == j
    float4 w = W4[idx];
    wc4[idx] = make_float4(w.x * c, w.y * c, w.z * c, w.w * c);
}

// -------- S-GEMM: spart[is][col][b] = sum over i in split of wc . x --------
// grid (4 b-tiles, 36 i-splits), 256 threads. Thread tile: 4 b x 10 cols.
__global__ __launch_bounds__(256) void s_gemm_kernel() {
    __shared__ float xs[8 * 64];     // [k][b]   per-capsule x tile
    __shared__ float ws[COLS * 8];   // [col][k] per-capsule scaled W (linear == global layout)

    const int b0    = blockIdx.x * 64;
    const int ibase = blockIdx.y * IPB;
    const int tid   = threadIdx.x;
    const int tx    = tid & 15;      // b sub-lane (4 b each)
    const int ty    = tid >> 4;      // col group (10 cols each)

    // prefetch register staging (hide L2 latency behind compute)
    const int id1 = tid + 256;
    const int xo0 = ((tid >> 6) * BATCH) + b0 + (tid & 63);
    const int xo1 = ((id1 >> 6) * BATCH) + b0 + (id1 & 63);

    float xr0, xr1, wr0, wr1, wr2, wr3, wr4;
    {
        int i = ibase;
        xr0 = g_xT[i * (8 * BATCH) + xo0];
        xr1 = g_xT[i * (8 * BATCH) + xo1];
        const float* wp = g_wc + i * (COLS * 8) + tid;
        wr0 = wp[0]; wr1 = wp[256]; wr2 = wp[512]; wr3 = wp[768]; wr4 = wp[1024];
    }

    float acc[4][10];
#pragma unroll
    for (int bb = 0; bb < 4; ++bb)
#pragma unroll
        for (int cc = 0; cc < 10; ++cc) acc[bb][cc] = 0.0f;

    for (int il = 0; il < IPB; ++il) {
        __syncthreads();
        xs[tid] = xr0; xs[id1] = xr1;
        ws[tid] = wr0; ws[tid + 256] = wr1; ws[tid + 512] = wr2;
        ws[tid + 768] = wr3; ws[tid + 1024] = wr4;
        __syncthreads();

        if (il < IPB - 1) {  // prefetch next capsule
            int i = ibase + il + 1;
            xr0 = g_xT[i * (8 * BATCH) + xo0];
            xr1 = g_xT[i * (8 * BATCH) + xo1];
            const float* wp = g_wc + i * (COLS * 8) + tid;
            wr0 = wp[0]; wr1 = wp[256]; wr2 = wp[512]; wr3 = wp[768]; wr4 = wp[1024];
        }

        const float4* xs4 = (const float4*)xs;   // [8][16]
        const float4* ws4 = (const float4*)ws;   // [160][2]
#pragma unroll
        for (int kq = 0; kq < 2; ++kq) {
            float4 xr[4];
#pragma unroll
            for (int kk = 0; kk < 4; ++kk) xr[kk] = xs4[(kq * 4 + kk) * 16 + tx];
            float4 wr[10];
#pragma unroll
            for (int cc = 0; cc < 10; ++cc) wr[cc] = ws4[(ty * 10 + cc) * 2 + kq];
#pragma unroll
            for (int kk = 0; kk < 4; ++kk) {
                float4 xv = xr[kk];
#pragma unroll
                for (int cc = 0; cc < 10; ++cc) {
                    float w = (kk == 0) ? wr[cc].x : (kk == 1) ? wr[cc].y
                            : (kk == 2) ? wr[cc].z : wr[cc].w;
                    acc[0][cc] = fmaf(xv.x, w, acc[0][cc]);
                    acc[1][cc] = fmaf(xv.y, w, acc[1][cc]);
                    acc[2][cc] = fmaf(xv.z, w, acc[2][cc]);
                    acc[3][cc] = fmaf(xv.w, w, acc[3][cc]);
                }
            }
        }
    }

    float* outp = g_spart + (size_t)blockIdx.y * (COLS * BATCH);
#pragma unroll
    for (int cc = 0; cc < 10; ++cc) {
        int col = ty * 10 + cc;
        float4 v = make_float4(acc[0][cc], acc[1][cc], acc[2][cc], acc[3][cc]);
        *(float4*)(outp + col * BATCH + b0 + tx * 4) = v;
    }
}

// -------- reduce split-K partials, squash, write vT + final output --------
__global__ void squash_kernel(float* __restrict__ out) {
    int j = blockIdx.x;        // 10
    int b = threadIdx.x;       // 256
    float sv[OUT_DIM];
#pragma unroll
    for (int d = 0; d < OUT_DIM; ++d) {
        const float* p = g_spart + (j * OUT_DIM + d) * BATCH + b;
        float a = 0.0f;
#pragma unroll
        for (int is = 0; is < ISPLIT; ++is) a += p[(size_t)is * (COLS * BATCH)];
        sv[d] = a;
    }
    float sq = 0.0f;
#pragma unroll
    for (int d = 0; d < OUT_DIM; ++d) sq += sv[d] * sv[d];
    // sq/(1+sq) * s/sqrt(sq)  ==  s * sqrt(sq)/(1+sq)
    float coef = sq * rsqrtf(sq) / (1.0f + sq);
#pragma unroll
    for (int d = 0; d < OUT_DIM; ++d) {
        float v = sv[d] * coef;
        g_vT[(j * OUT_DIM + d) * BATCH + b] = v;
        out[b * COLS + j * OUT_DIM + d] = v;
    }
}

// -------- b-logit update: fused T-GEMM (xT @ vT^T per capsule) + W contraction --------
// grid 288 (4 capsules each), 640 threads: thread = (i_loc in 0..3, col in 0..159), acc over 8 k.
__global__ __launch_bounds__(640) void b_update_kernel(const float* __restrict__ W) {
    __shared__ float vs[32 * 165];      // [bb][col], padded row 165 -> conflict-free
    __shared__ float xs[4 * 32 * 8];    // [i_loc][bb][k]
    __shared__ float bsum[40];

    const int ig  = blockIdx.x;
    const int tid = threadIdx.x;
    if (tid < 40) bsum[tid] = 0.0f;
    const int col = tid % 160;
    const int il  = tid / 160;

    float acc[8];
#pragma unroll
    for (int k = 0; k < 8; ++k) acc[k] = 0.0f;

    for (int cb = 0; cb < 8; ++cb) {
        const int b0 = cb * 32;
        __syncthreads();
        for (int idx = tid; idx < COLS * 32; idx += 640) {
            int c2 = idx >> 5, bb = idx & 31;
            vs[bb * 165 + c2] = g_vT[c2 * BATCH + b0 + bb];
        }
        for (int idx = tid; idx < 4 * 8 * 32; idx += 640) {
            int ikl = idx >> 5, bb = idx & 31;
            int i_l = ikl >> 3, k = ikl & 7;
            xs[(i_l * 32 + bb) * 8 + k] = g_xT[(((ig * 4 + i_l) * 8 + k) * BATCH) + b0 + bb];
        }
        __syncthreads();

        const float* xrow = &xs[(il * 32) * 8];
#pragma unroll 8
        for (int bb = 0; bb < 32; ++bb) {
            float vv = vs[bb * 165 + col];
            float4 xa = *(const float4*)&xrow[bb * 8];
            float4 xb = *(const float4*)&xrow[bb * 8 + 4];
            acc[0] = fmaf(xa.x, vv, acc[0]); acc[1] = fmaf(xa.y, vv, acc[1]);
            acc[2] = fmaf(xa.z, vv, acc[2]); acc[3] = fmaf(xa.w, vv, acc[3]);
            acc[4] = fmaf(xb.x, vv, acc[4]); acc[5] = fmaf(xb.y, vv, acc[5]);
            acc[6] = fmaf(xb.z, vv, acc[6]); acc[7] = fmaf(xb.w, vv, acc[7]);
        }
    }

    // contract T[i, k, col] with W[i, col, k] -> partial b-delta, reduce over d within j
    const int i = ig * 4 + il;
    const float4* w4 = (const float4*)(W + (size_t)i * (COLS * 8) + col * 8);
    float4 wa = w4[0], wb = w4[1];
    float p = wa.x * acc[0] + wa.y * acc[1] + wa.z * acc[2] + wa.w * acc[3]
            + wb.x * acc[4] + wb.y * acc[5] + wb.z * acc[6] + wb.w * acc[7];
    atomicAdd(&bsum[il * 10 + (col >> 4)], p);
    __syncthreads();
    if (tid < 40) {
        int ii = ig * 4 + tid / 10, jj = tid % 10;
        g_b[ii * OUT_NODES + jj] += bsum[tid] * (1.0f / (float)BATCH);
    }
}

// -------- launch sequence (graph-capturable: kernels only) --------
extern "C" void kernel_launch(void* const* d_in, const int* in_sizes, int n_in,
                              void* d_out, int out_size) {
    const float* x = (const float*)d_in[0];   // [256,1152,8]
    const float* W = (const float*)d_in[1];   // [1152,10,16,8]
    float* out = (float*)d_out;               // [256,10,16,1]

    zero_b_kernel<<<45, 256>>>();
    transpose_x_kernel<<<dim3(KTOT / 32, BATCH / 32), dim3(32, 8)>>>(x);

    for (int t = 0; t < 3; ++t) {
        softmax_c_kernel<<<9, 128>>>();
        scale_w_kernel<<<1440, 256>>>(W);
        s_gemm_kernel<<<dim3(4, ISPLIT), 256>>>();
        squash_kernel<<<10, 256>>>(out);
        if (t < 2) b_update_kernel<<<288, 640>>>(W);
    }
}

// round 2
// speedup vs baseline: 1.4576x; 1.4576x over previous
#include <cuda_runtime.h>

#define IN_NODES  1152
#define OUT_NODES 10
#define IN_DIM    8
#define OUT_DIM   16
#define BATCH     256
#define COLS      160                     // OUT_NODES * OUT_DIM
#define KTOT      (IN_NODES * IN_DIM)     // 9216
#define ISPLIT    144                     // capsule groups (8 capsules each)
#define CPB       8                       // capsules per block

// ---------------- device scratch ----------------
__device__ float g_xT   [KTOT * BATCH];                 // x transposed [ik][b]
__device__ float g_spart[ISPLIT * COLS * BATCH];        // s partials [grp][col][b]  (23.6MB)
__device__ float g_vB   [BATCH * COLS];                 // v, batch-major [b][col]
__device__ float g_b    [IN_NODES * OUT_NODES];         // routing logits

// ---------------- transpose x [256][9216] -> xT [9216][256] ----------------
__global__ void transpose_x_kernel(const float* __restrict__ x) {
    __shared__ float tile[32][33];
    int ik0 = blockIdx.x * 32;
    int b0  = blockIdx.y * 32;
    int tx = threadIdx.x, ty = threadIdx.y;  // 32 x 8
#pragma unroll
    for (int r = 0; r < 32; r += 8)
        tile[ty + r][tx] = x[(size_t)(b0 + ty + r) * KTOT + ik0 + tx];
    __syncthreads();
#pragma unroll
    for (int r = 0; r < 32; r += 8)
        g_xT[(size_t)(ik0 + ty + r) * BATCH + b0 + tx] = tile[tx][ty + r];
}

// ---------------- fused kernel: b-update + softmax + s-GEMM ----------------
// mode 0: s-GEMM only, c = 0.1 (first iteration, b==0)
// mode 1: b-update with previous b == 0, then softmax + s-GEMM
// mode 2: full (read g_b, update, softmax, s-GEMM)
// grid = 144 blocks, 256 threads; block owns capsules [i0, i0+8), full batch.
// Dynamic smem: phase A {vs[32][160], xs[8][8][32]}, phase B {ws[10240], xb[8][8][64]}
__global__ __launch_bounds__(256) void f_kernel(const float* __restrict__ W, int mode) {
    extern __shared__ float sm[];
    __shared__ float bsum[80];   // [ic][j] partial b-deltas
    __shared__ float cs[80];     // [ic][j] softmax coefficients

    const int i0  = blockIdx.x * CPB;
    const int tid = threadIdx.x;

    if (mode > 0) {
        // ---------- Phase A: T[i,k,col] = sum_b xT[ik,b] * vB[b,col] ----------
        float* vs = sm;          // [bb][160]
        float* xs = sm + 5120;   // [ic][k][32]
        const int ic   = tid >> 5;    // warp == capsule
        const int lane = tid & 31;

        float acc[5][8];
#pragma unroll
        for (int cc = 0; cc < 5; ++cc)
#pragma unroll
            for (int k = 0; k < 8; ++k) acc[cc][k] = 0.0f;

        for (int cb = 0; cb < 8; ++cb) {
            const int b0 = cb * 32;
            __syncthreads();
            for (int idx = tid; idx < 5120; idx += 256)
                vs[idx] = g_vB[b0 * COLS + idx];
            for (int idx = tid; idx < 2048; idx += 256) {
                int ic2 = idx >> 8, k = (idx >> 5) & 7, bb = idx & 31;
                xs[idx] = g_xT[((size_t)(i0 + ic2) * 8 + k) * BATCH + b0 + bb];
            }
            __syncthreads();

#pragma unroll 4
            for (int bb = 0; bb < 32; ++bb) {
                float xk[8];
#pragma unroll
                for (int k = 0; k < 8; ++k) xk[k] = xs[ic * 256 + k * 32 + bb];
#pragma unroll
                for (int cc = 0; cc < 5; ++cc) {
                    float vv = vs[bb * COLS + lane + 32 * cc];
#pragma unroll
                    for (int k = 0; k < 8; ++k)
                        acc[cc][k] = fmaf(xk[k], vv, acc[cc][k]);
                }
            }
        }

        // ---------- contract with W -> delta-b, deterministic shfl reduce ----------
#pragma unroll
        for (int cc = 0; cc < 5; ++cc) {
            int col = lane + 32 * cc;
            const float4* w4 = (const float4*)(W + ((size_t)(i0 + ic) * COLS + col) * 8);
            float4 wa = w4[0], wb = w4[1];
            float p = wa.x * acc[cc][0] + wa.y * acc[cc][1] + wa.z * acc[cc][2] + wa.w * acc[cc][3]
                    + wb.x * acc[cc][4] + wb.y * acc[cc][5] + wb.z * acc[cc][6] + wb.w * acc[cc][7];
            // lanes 0..15 share j = 2cc, lanes 16..31 share j = 2cc+1
#pragma unroll
            for (int off = 8; off; off >>= 1)
                p += __shfl_xor_sync(0xffffffffu, p, off, 16);
            if ((lane & 15) == 0)
                bsum[ic * 10 + 2 * cc + (lane >> 4)] = p;
        }
        __syncthreads();

        // ---------- update b, per-capsule softmax ----------
        if (tid < 80) {
            float bn = bsum[tid] * (1.0f / (float)BATCH);
            if (mode == 2) bn += g_b[i0 * OUT_NODES + tid];
            g_b[i0 * OUT_NODES + tid] = bn;
            bsum[tid] = bn;   // reuse as brow
        }
        __syncthreads();
        if (tid < 8) {
            float m = -1e30f;
#pragma unroll
            for (int j = 0; j < 10; ++j) m = fmaxf(m, bsum[tid * 10 + j]);
            float e[10], s = 0.0f;
#pragma unroll
            for (int j = 0; j < 10; ++j) { e[j] = __expf(bsum[tid * 10 + j] - m); s += e[j]; }
            float inv = 1.0f / s;
#pragma unroll
            for (int j = 0; j < 10; ++j) cs[tid * 10 + j] = e[j] * inv;
        }
        __syncthreads();
    }

    // ---------- Phase B: spart[grp][col][b] = sum_{ic,k} (c*W)[i,col,k] * xT[ik,b] ----------
    float* ws = sm;            // [ic][col][k] scaled W, 10240 floats
    float* xb = sm + 10240;    // [ic][k][64], 4096 floats
    const int tx = tid & 15;   // 4 b each
    const int ty = tid >> 4;   // 10 cols each

    for (int ch = 0; ch < 4; ++ch) {
        const int b0 = ch * 64;
        __syncthreads();
        if (ch == 0) {
            const float4* W4 = (const float4*)(W + (size_t)i0 * 1280);
            float4* ws4v = (float4*)ws;
            for (int q = tid; q < 2560; q += 256) {
                int ic2 = q / 320, r = q - ic2 * 320;
                float c = (mode == 0) ? 0.1f : cs[ic2 * 10 + (r >> 5)];
                float4 w = W4[q];
                ws4v[q] = make_float4(w.x * c, w.y * c, w.z * c, w.w * c);
            }
        }
        for (int idx = tid; idx < 4096; idx += 256) {
            int ic2 = idx >> 9, k = (idx >> 6) & 7, bb = idx & 63;
            xb[idx] = g_xT[((size_t)(i0 + ic2) * 8 + k) * BATCH + b0 + bb];
        }
        __syncthreads();

        float accB[4][10];
#pragma unroll
        for (int bb = 0; bb < 4; ++bb)
#pragma unroll
            for (int cc = 0; cc < 10; ++cc) accB[bb][cc] = 0.0f;

        const float4* xb4 = (const float4*)xb;
        const float4* ws4 = (const float4*)ws;
        for (int ic2 = 0; ic2 < CPB; ++ic2) {
#pragma unroll
            for (int kq = 0; kq < 2; ++kq) {
                float4 xr[4];
#pragma unroll
                for (int kk = 0; kk < 4; ++kk)
                    xr[kk] = xb4[(ic2 * 8 + kq * 4 + kk) * 16 + tx];
                float4 wr[10];
#pragma unroll
                for (int cc = 0; cc < 10; ++cc)
                    wr[cc] = ws4[ic2 * 320 + (ty * 10 + cc) * 2 + kq];
#pragma unroll
                for (int kk = 0; kk < 4; ++kk) {
                    float4 xv = xr[kk];
#pragma unroll
                    for (int cc = 0; cc < 10; ++cc) {
                        float w = (kk == 0) ? wr[cc].x : (kk == 1) ? wr[cc].y
                                : (kk == 2) ? wr[cc].z : wr[cc].w;
                        accB[0][cc] = fmaf(xv.x, w, accB[0][cc]);
                        accB[1][cc] = fmaf(xv.y, w, accB[1][cc]);
                        accB[2][cc] = fmaf(xv.z, w, accB[2][cc]);
                        accB[3][cc] = fmaf(xv.w, w, accB[3][cc]);
                    }
                }
            }
        }

        float* outp = g_spart + (size_t)blockIdx.x * (COLS * BATCH);
#pragma unroll
        for (int cc = 0; cc < 10; ++cc) {
            int col = ty * 10 + cc;
            *(float4*)(outp + col * BATCH + b0 + tx * 4) =
                make_float4(accB[0][cc], accB[1][cc], accB[2][cc], accB[3][cc]);
        }
    }
}

// ---------------- squash: reduce 144 partials, normalize, write vB (+out) ----------------
// grid (10 j, 16 b-groups), 256 threads = (isg 16) x (b_loc 16)
__global__ __launch_bounds__(256) void squash_kernel(float* __restrict__ out, int write_out) {
    __shared__ float red[16][16][17];
    const int j  = blockIdx.x;
    const int b0 = blockIdx.y * 16;
    const int tid = threadIdx.x;
    const int b_loc = tid & 15, isg = tid >> 4;

    float acc[16];
#pragma unroll
    for (int d = 0; d < 16; ++d) acc[d] = 0.0f;
    for (int t = 0; t < 9; ++t) {
        int is = isg * 9 + t;
        const float* p = g_spart + ((size_t)is * COLS + j * 16) * BATCH + b0 + b_loc;
#pragma unroll
        for (int d = 0; d < 16; ++d) acc[d] += p[d * BATCH];
    }
#pragma unroll
    for (int d = 0; d < 16; ++d) red[isg][d][b_loc] = acc[d];
    __syncthreads();

    const int b2 = tid >> 4, d2 = tid & 15;
    float sv = 0.0f;
#pragma unroll
    for (int g = 0; g < 16; ++g) sv += red[g][d2][b2];

    float sq = sv * sv;
#pragma unroll
    for (int off = 8; off; off >>= 1)
        sq += __shfl_xor_sync(0xffffffffu, sq, off, 16);
    float coef = sq * rsqrtf(sq) / (1.0f + sq);
    float v = sv * coef;

    g_vB[(size_t)(b0 + b2) * COLS + j * 16 + d2] = v;
    if (write_out)
        out[(size_t)(b0 + b2) * COLS + j * 16 + d2] = v;
}

// ---------------- launch sequence ----------------
extern "C" void kernel_launch(void* const* d_in, const int* in_sizes, int n_in,
                              void* d_out, int out_size) {
    const float* x = (const float*)d_in[0];   // [256,1152,8]
    const float* W = (const float*)d_in[1];   // [1152,10,16,8]
    float* out = (float*)d_out;               // [256,10,16,1] == [b][160]

    const int FSMEM = (10240 + 4096) * 4;     // 57344 bytes (phase-B union is the max)
    cudaFuncSetAttribute(f_kernel, cudaFuncAttributeMaxDynamicSharedMemorySize, FSMEM);

    transpose_x_kernel<<<dim3(KTOT / 32, BATCH / 32), dim3(32, 8)>>>(x);

    f_kernel<<<ISPLIT, 256, FSMEM>>>(W, 0);       // iter 1: c = 0.1 exactly
    squash_kernel<<<dim3(10, 16), 256>>>(out, 0);
    f_kernel<<<ISPLIT, 256, FSMEM>>>(W, 1);       // iter 2: b-update (prev b = 0) + softmax + s
    squash_kernel<<<dim3(10, 16), 256>>>(out, 0);
    f_kernel<<<ISPLIT, 256, FSMEM>>>(W, 2);       // iter 3: full
    squash_kernel<<<dim3(10, 16), 256>>>(out, 1); // final v -> output
}